// round 13
// baseline (speedup 1.0000x reference)
#include <cuda_runtime.h>
#include <math.h>

#define NMAX 100352
#define BN_EPS 1e-3f

__device__ float g_emb [NMAX * 32];
__device__ float g_u   [NMAX * 32];
__device__ float g_v   [NMAX * 32];
__device__ float g_max [NMAX * 32];
__device__ float g_sums[128];      // fp32 stats: [0:32) s1, [32:64) q1, [64:96) s2, [96:128) q2

__device__ unsigned g_bar_count = 0;
__device__ unsigned g_bar_gen   = 0;

typedef unsigned long long u64;

__device__ __forceinline__ u64 pack2(float x, float y) {
    u64 r; asm("mov.b64 %0, {%1, %2};" : "=l"(r) : "f"(x), "f"(y)); return r;
}
__device__ __forceinline__ void unpack2(u64 v, float& x, float& y) {
    asm("mov.b64 {%0, %1}, %2;" : "=f"(x), "=f"(y) : "l"(v));
}
__device__ __forceinline__ u64 ffma2(u64 a, u64 b, u64 c) {
    u64 d; asm("fma.rn.f32x2 %0, %1, %2, %3;" : "=l"(d) : "l"(a), "l"(b), "l"(c)); return d;
}
__device__ __forceinline__ u64 add2(u64 a, u64 b) {
    u64 d; asm("add.rn.f32x2 %0, %1, %2;" : "=l"(d) : "l"(a), "l"(b)); return d;
}
__device__ __forceinline__ float eluf(float x) { return x > 0.f ? x : expm1f(x); }

__global__ void k_zero() {
    if (threadIdx.x < 128) g_sums[threadIdx.x] = 0.f;
}

// all blocks must be resident (grid == guaranteed-resident capacity via launch_bounds)
__device__ __forceinline__ void grid_barrier() {
    __syncthreads();
    if (threadIdx.x == 0) {
        __threadfence();
        unsigned gen = *(volatile unsigned*)&g_bar_gen;
        unsigned arrived = atomicAdd(&g_bar_count, 1u);
        if (arrived == gridDim.x - 1) {
            g_bar_count = 0;
            __threadfence();
            atomicAdd(&g_bar_gen, 1u);
        } else {
            while (*(volatile unsigned*)&g_bar_gen == gen) {}
        }
        __threadfence();
    }
    __syncthreads();
}

__device__ __forceinline__ void flush_stats(float accs, float accq, int sumoff) {
    __shared__ float ss[4][32], sq[4][32];
    int lane = threadIdx.x & 31;
    int w    = threadIdx.x >> 5;
    ss[w][lane] = accs;
    sq[w][lane] = accq;
    __syncthreads();
    if (threadIdx.x < 32) {
        float s = 0.f, q = 0.f;
        #pragma unroll
        for (int k = 0; k < 4; k++) { s += ss[k][lane]; q += sq[k][lane]; }
        atomicAdd(&g_sums[sumoff + lane],      s);
        atomicAdd(&g_sums[sumoff + 32 + lane], q);
        __threadfence();
    }
    __syncthreads();
}

// ================= FUSED 1: encode -> BN1 stats -> barrier -> prep ==========
// weights live in SMEM (duplicated u64) -> regs ~50 -> 8 blocks/SM
__global__ void __launch_bounds__(128, 8) k_enc_prep(
        const float* __restrict__ x_cont, const int* __restrict__ x_cat,
        const float* __restrict__ datanorm,
        const float* __restrict__ W_cont, const float* __restrict__ b_cont,
        const float* __restrict__ emb_charge, const float* __restrict__ emb_pdg,
        const float* __restrict__ W_cat, const float* __restrict__ b_cat,
        const float* __restrict__ W_enc, const float* __restrict__ b_enc,
        const float* __restrict__ g_all, const float* __restrict__ be_all,
        const float* __restrict__ W_msg, int N)
{
    int tid  = threadIdx.x;
    int lane = tid & 31;
    int w    = tid >> 5;
    int l16  = lane & 15;
    bool hi  = lane >= 16;
    int gw   = (blockIdx.x * blockDim.x + tid) >> 5;
    int nw   = (gridDim.x * blockDim.x) >> 5;

    __shared__ __align__(16) u64 sWenc [32][32];  // phase A: W_enc dup; phase B: folded W_msg
    __shared__ __align__(16) u64 sWcat [16][16];
    __shared__ __align__(16) u64 sWcont[6][16];
    __shared__ __align__(16) u64 s_c [4][16];
    __shared__ __align__(16) u64 s_x [4][8];
    __shared__ __align__(16) u64 s_in[4][32];
    __shared__ __align__(16) u64 s_h [4][2][32];

    // load weights to smem (duplicated u64)
    for (int idx = tid; idx < 1024; idx += 128) {
        float v = W_enc[idx];
        sWenc[idx >> 5][idx & 31] = pack2(v, v);
    }
    for (int idx = tid; idx < 256; idx += 128) {
        float v = W_cat[idx];
        sWcat[idx >> 4][idx & 15] = pack2(v, v);
    }
    if (tid < 96) {
        float v = W_cont[tid];
        sWcont[tid >> 4][tid & 15] = pack2(v, v);
    }
    __syncthreads();

    // ---------------- phase A: encoder ----------------
    {
        float bcat  = b_cat[l16];
        float bcont = b_cont[l16];
        float benc  = b_enc[lane];
        float dn    = (lane < 6) ? datanorm[lane] : 0.f;

        const float ninf = __int_as_float(0xff800000);
        float accs = 0.f, accq = 0.f;

        for (long long n0 = (long long)gw * 2; n0 < N; n0 += (long long)nw * 2) {
            int na = (int)n0;
            bool hasb = (na + 1 < N);
            int nb = hasb ? na + 1 : na;

            if (!hi) {
                int2 ca = __ldg((const int2*)x_cat + na);
                int2 cb = __ldg((const int2*)x_cat + nb);
                int pa = ca.x < 0 ? -ca.x : ca.x;
                int pb = cb.x < 0 ? -cb.x : cb.x;
                int pia = (pa == 1) ? 0 : (pa == 2) ? 1 : (pa == 11) ? 2 : (pa == 13) ? 3
                        : (pa == 22) ? 4 : (pa == 130) ? 5 : 6;
                int pib = (pb == 1) ? 0 : (pb == 2) ? 1 : (pb == 11) ? 2 : (pb == 13) ? 3
                        : (pb == 22) ? 4 : (pb == 130) ? 5 : 6;
                float c0a = (lane < 8) ? emb_charge[(ca.y + 1) * 8 + lane] : emb_pdg[pia * 8 + lane - 8];
                float c0b = (lane < 8) ? emb_charge[(cb.y + 1) * 8 + lane] : emb_pdg[pib * 8 + lane - 8];
                s_c[w][lane] = pack2(c0a, c0b);
                if (lane < 6) {
                    float xa = x_cont[(long long)na * 6 + lane] * dn;
                    float xb = x_cont[(long long)nb * 6 + lane] * dn;
                    s_x[w][lane] = pack2(xa, xb);
                }
            }
            __syncwarp();

            u64 in2;
            if (!hi) {
                u64 a0 = pack2(bcat, bcat), a1 = pack2(0.f, 0.f);
                const ulonglong2* p = (const ulonglong2*)s_c[w];
                #pragma unroll
                for (int i = 0; i < 4; i++) {
                    ulonglong2 qa = p[i];
                    ulonglong2 qb = p[i + 4];
                    a0 = ffma2(qa.x, sWcat[2 * i][l16], a0);
                    a0 = ffma2(qa.y, sWcat[2 * i + 1][l16], a0);
                    a1 = ffma2(qb.x, sWcat[2 * i + 8][l16], a1);
                    a1 = ffma2(qb.y, sWcat[2 * i + 9][l16], a1);
                }
                u64 acc = add2(a0, a1);
                float v0, v1; unpack2(acc, v0, v1);
                in2 = pack2(eluf(v0), eluf(v1));
            } else {
                u64 acc = pack2(bcont, bcont);
                const ulonglong2* p = (const ulonglong2*)s_x[w];
                #pragma unroll
                for (int i = 0; i < 3; i++) {
                    ulonglong2 q = p[i];
                    acc = ffma2(q.x, sWcont[2 * i][l16], acc);
                    acc = ffma2(q.y, sWcont[2 * i + 1][l16], acc);
                }
                float v0, v1; unpack2(acc, v0, v1);
                in2 = pack2(eluf(v0), eluf(v1));
            }
            s_in[w][lane] = in2;
            __syncwarp();

            u64 a0 = pack2(benc, benc), a1 = pack2(0.f, 0.f);
            {
                const ulonglong2* p = (const ulonglong2*)s_in[w];
                #pragma unroll
                for (int i = 0; i < 8; i++) {
                    ulonglong2 qa = p[i];
                    ulonglong2 qb = p[i + 8];
                    a0 = ffma2(qa.x, sWenc[2 * i][lane], a0);
                    a0 = ffma2(qa.y, sWenc[2 * i + 1][lane], a0);
                    a1 = ffma2(qb.x, sWenc[2 * i + 16][lane], a1);
                    a1 = ffma2(qb.y, sWenc[2 * i + 17][lane], a1);
                }
            }
            u64 acc = add2(a0, a1);
            float ha, hb; unpack2(acc, ha, hb);
            ha = eluf(ha); hb = eluf(hb);

            g_emb[(long long)na * 32 + lane] = ha;
            g_max[(long long)na * 32 + lane] = ninf;
            accs += ha; accq += ha * ha;
            if (hasb) {
                g_emb[(long long)nb * 32 + lane] = hb;
                g_max[(long long)nb * 32 + lane] = ninf;
                accs += hb; accq += hb * hb;
            }
            __syncwarp();
        }
        flush_stats(accs, accq, 0);
    }

    grid_barrier();

    // ---------------- phase B: u,v with BN1 folded (weights into sWenc) -----
    u64 base;
    {
        float m    = g_sums[lane] / (float)N;
        float var  = g_sums[32 + lane] / (float)N - m * m;
        float inv  = rsqrtf(var + BN_EPS);
        float ga   = g_all[lane];
        float scale = ga * inv;
        float shift = be_all[lane] - m * ga * inv;

        float cu = 0.f, cv = 0.f;
        for (int j = 0; j < 32; j++) {
            float a = W_msg[j * 32 + lane];
            float b = W_msg[1024 + j * 32 + lane];
            float wdj = a - b;
            float wbj = b;
            float sj = __shfl_sync(0xffffffffu, scale, j);
            float tj = __shfl_sync(0xffffffffu, shift, j);
            cu += tj * wdj;
            cv += tj * wbj;
            sWenc[j][lane] = pack2(wdj * sj, wbj * sj);  // all warps write same values
        }
        base = pack2(cu, cv);
    }
    __syncthreads();

    {
        const u64 zz = pack2(0.f, 0.f);

        long long n0 = (long long)gw * 2;
        float ha = (n0 < N) ? g_emb[n0 * 32 + lane] : 0.f;
        float hb = (n0 + 1 < N) ? g_emb[(n0 + 1) * 32 + lane] : ha;

        for (; n0 < N; n0 += (long long)nw * 2) {
            int na = (int)n0;
            bool hasb = (na + 1 < N);
            int nb = hasb ? na + 1 : na;

            s_h[w][0][lane] = pack2(ha, ha);
            s_h[w][1][lane] = pack2(hb, hb);
            __syncwarp();

            long long nn = n0 + (long long)nw * 2;
            float nha = 0.f, nhb = 0.f;
            if (nn < N) {
                nha = g_emb[nn * 32 + lane];
                nhb = (nn + 1 < N) ? g_emb[(nn + 1) * 32 + lane] : nha;
            }

            u64 a0 = base, a1 = zz, b0 = base, b1 = zz;
            const ulonglong2* p0 = (const ulonglong2*)s_h[w][0];
            const ulonglong2* p1 = (const ulonglong2*)s_h[w][1];
            #pragma unroll
            for (int i = 0; i < 8; i++) {
                u64 w0 = sWenc[2 * i][lane];
                u64 w1 = sWenc[2 * i + 1][lane];
                u64 w16 = sWenc[2 * i + 16][lane];
                u64 w17 = sWenc[2 * i + 17][lane];
                ulonglong2 qa = p0[i];
                ulonglong2 qb = p0[i + 8];
                a0 = ffma2(qa.x, w0, a0);
                a0 = ffma2(qa.y, w1, a0);
                a1 = ffma2(qb.x, w16, a1);
                a1 = ffma2(qb.y, w17, a1);
                ulonglong2 ra = p1[i];
                ulonglong2 rb = p1[i + 8];
                b0 = ffma2(ra.x, w0, b0);
                b0 = ffma2(ra.y, w1, b0);
                b1 = ffma2(rb.x, w16, b1);
                b1 = ffma2(rb.y, w17, b1);
            }
            u64 acc0 = add2(a0, a1);
            u64 acc1 = add2(b0, b1);
            float u0, v0; unpack2(acc0, u0, v0);
            g_u[(long long)na * 32 + lane] = u0;
            g_v[(long long)na * 32 + lane] = v0;
            if (hasb) {
                float u1, v1; unpack2(acc1, u1, v1);
                g_u[(long long)nb * 32 + lane] = u1;
                g_v[(long long)nb * 32 + lane] = v1;
            }
            ha = nha; hb = nhb;
            __syncwarp();
        }
    }
}

// ---------------- K3: edge atomic max (proven config) -----------------------
__device__ __forceinline__ void amax1(float* a, float v, float c) {
    if (v > c) {
        if (__float_as_int(v) >= 0) atomicMax((int*)a, __float_as_int(v));
        else                        atomicMin((unsigned int*)a, __float_as_uint(v));
    }
}

__global__ void __launch_bounds__(256) k_edge(const int* __restrict__ ei, int E, int NP)
{
    int tid = blockIdx.x * blockDim.x + threadIdx.x;
    int c  = tid & 7;
    int pe = tid >> 3;
    if (pe >= NP) return;
    int e0 = pe * 2;
    bool has1 = (e0 + 1 < E);

    int s0, s1, d0, d1;
    if ((E & 1) == 0) {
        int2 ss = __ldg((const int2*)(ei + e0));
        int2 dd = __ldg((const int2*)(ei + E + e0));
        s0 = ss.x; s1 = ss.y;
        d0 = dd.x; d1 = dd.y;
    } else {
        s0 = __ldg(&ei[e0]);
        d0 = __ldg(&ei[E + e0]);
        s1 = has1 ? __ldg(&ei[e0 + 1])     : s0;
        d1 = has1 ? __ldg(&ei[E + e0 + 1]) : d0;
    }

    const float4* v4 = (const float4*)g_v;
    const float4* m4 = (const float4*)g_max;

    float4 val0 = __ldg(&v4[(long long)s0 * 8 + c]);
    float4 val1 = __ldg(&v4[(long long)s1 * 8 + c]);
    // monotone buffer: stale pre-read only causes a redundant atomic, never a miss
    float4 cur0 = __ldg(&m4[(long long)d0 * 8 + c]);
    float4 cur1 = __ldg(&m4[(long long)d1 * 8 + c]);

    float* a0 = &g_max[(long long)d0 * 32 + c * 4];
    amax1(a0 + 0, val0.x, cur0.x);
    amax1(a0 + 1, val0.y, cur0.y);
    amax1(a0 + 2, val0.z, cur0.z);
    amax1(a0 + 3, val0.w, cur0.w);
    if (has1) {
        float* a1 = &g_max[(long long)d1 * 32 + c * 4];
        amax1(a1 + 0, val1.x, cur1.x);
        amax1(a1 + 1, val1.y, cur1.y);
        amax1(a1 + 2, val1.z, cur1.z);
        amax1(a1 + 3, val1.w, cur1.w);
    }
}

// ========= FUSED 2: agg stats (stash agg) -> barrier -> output MLP ==========
// (R11 measured config: 8 blocks/SM, 1184 blocks, chunk <= 22)
__global__ void __launch_bounds__(128, 8) k_agg_out(
        const float* __restrict__ g_all, const float* __restrict__ be_all,
        const float* __restrict__ b_msg,
        const float* __restrict__ g_conv, const float* __restrict__ be_conv,
        const float* __restrict__ W_o1, const float* __restrict__ b_o1,
        const float* __restrict__ W_o2, const float* __restrict__ b_o2,
        float* __restrict__ out, int N)
{
    int lane = threadIdx.x & 31;
    int w    = threadIdx.x >> 5;
    int l16  = lane & 15;
    int gw   = blockIdx.x * 4 + w;
    int nwarps = gridDim.x * 4;
    int chunk  = (N + nwarps - 1) / nwarps;
    int n_start = gw * chunk;
    int cnt = N - n_start;
    if (cnt > chunk) cnt = chunk;
    if (cnt < 0) cnt = 0;

    __shared__ float s_agg[4][22][32];
    __shared__ float s_h[4][66];

    float bmr = b_msg[lane];

    // ---------------- phase A: agg + BN2 stats, stash agg in smem -----------
    {
        float accs = 0.f, accq = 0.f;
        for (int i = 0; i < cnt; i++) {
            long long n = (long long)(n_start + i);
            float mval = g_max[n * 32 + lane];
            float uval = g_u[n * 32 + lane];
            int m0 = __shfl_sync(0xffffffffu, __float_as_int(mval), 0);
            float x = (m0 == (int)0xff800000) ? 0.f : (uval + bmr + mval);
            s_agg[w][i][lane] = x;
            accs += x;
            accq += x * x;
        }
        flush_stats(accs, accq, 64);
    }

    grid_barrier();

    // ---------------- phase B: residual + output MLP (split-lane) -----------
    {
        float w1[32];
        #pragma unroll
        for (int j = 0; j < 32; j++) w1[j] = W_o1[j * 16 + l16];
        float w2s = W_o2[l16];
        float b1  = b_o1[l16];
        float b2  = b_o2[0];

        float m1    = g_sums[lane] / (float)N;
        float var1  = g_sums[32 + lane] / (float)N - m1 * m1;
        float inv1  = rsqrtf(var1 + BN_EPS);
        float ga    = g_all[lane];
        float scale1 = ga * inv1;
        float shift1 = be_all[lane] - m1 * ga * inv1;

        float m2    = g_sums[64 + lane] / (float)N;
        float var2  = g_sums[96 + lane] / (float)N - m2 * m2;
        float inv2  = rsqrtf(var2 + BN_EPS);
        float gc    = g_conv[lane];
        float scale2 = gc * inv2;
        float shift2 = be_conv[lane] - m2 * gc * inv2;

        int base = (lane < 16) ? 0 : 33;

        for (int i = 0; i < cnt; i += 2) {
            long long na = (long long)(n_start + i);
            bool hasb = (i + 1 < cnt);

            float hraw_a = g_emb[na * 32 + lane];
            float hraw_b = hasb ? g_emb[(na + 1) * 32 + lane] : 0.f;
            float h_a = (hraw_a * scale1 + shift1) + (s_agg[w][i][lane] * scale2 + shift2);
            float h_b = hasb ? (hraw_b * scale1 + shift1) + (s_agg[w][i + 1][lane] * scale2 + shift2) : 0.f;

            s_h[w][lane]      = h_a;
            s_h[w][33 + lane] = h_b;
            __syncwarp();

            float a0 = b1, a1 = 0.f;
            #pragma unroll
            for (int j = 0; j < 16; j++) {
                a0 += s_h[w][base + j]      * w1[j];
                a1 += s_h[w][base + 16 + j] * w1[16 + j];
            }
            float o = eluf(a0 + a1) * w2s;
            #pragma unroll
            for (int off = 1; off < 16; off <<= 1)
                o += __shfl_xor_sync(0xffffffffu, o, off);
            if (lane == 0)          out[na]     = o + b2;
            if (lane == 16 && hasb) out[na + 1] = o + b2;
            __syncwarp();
        }
    }
}

extern "C" void kernel_launch(void* const* d_in, const int* in_sizes, int n_in,
                              void* d_out, int out_size)
{
    const float* x_cont     = (const float*)d_in[0];
    const int*   x_cat      = (const int*)  d_in[1];
    const int*   edge_index = (const int*)  d_in[2];
    const float* datanorm   = (const float*)d_in[4];
    const float* W_cont     = (const float*)d_in[5];
    const float* b_cont     = (const float*)d_in[6];
    const float* emb_charge = (const float*)d_in[7];
    const float* emb_pdg    = (const float*)d_in[8];
    const float* W_cat      = (const float*)d_in[9];
    const float* b_cat      = (const float*)d_in[10];
    const float* W_enc      = (const float*)d_in[11];
    const float* b_enc      = (const float*)d_in[12];
    const float* g_all      = (const float*)d_in[13];
    const float* be_all     = (const float*)d_in[14];
    const float* W_msg      = (const float*)d_in[15];
    const float* b_msg      = (const float*)d_in[16];
    const float* g_conv     = (const float*)d_in[17];
    const float* be_conv    = (const float*)d_in[18];
    const float* W_o1       = (const float*)d_in[19];
    const float* b_o1       = (const float*)d_in[20];
    const float* W_o2       = (const float*)d_in[21];
    const float* b_o2       = (const float*)d_in[22];
    float* out = (float*)d_out;

    int N = in_sizes[0] / 6;
    int E = in_sizes[2] / 2;

    k_zero<<<1, 128>>>();
    k_enc_prep<<<1184, 128>>>(x_cont, x_cat, datanorm, W_cont, b_cont,
                              emb_charge, emb_pdg, W_cat, b_cat, W_enc, b_enc,
                              g_all, be_all, W_msg, N);
    int NP = (E + 1) / 2;
    long long tot = (long long)NP * 8;
    int eb = (int)((tot + 255) / 256);
    k_edge<<<eb, 256>>>(edge_index, E, NP);
    k_agg_out<<<1184, 128>>>(g_all, be_all, b_msg, g_conv, be_conv,
                             W_o1, b_o1, W_o2, b_o2, out, N);
}

// round 14
// speedup vs baseline: 1.1277x; 1.1277x over previous
#include <cuda_runtime.h>
#include <math.h>

#define NMAX 100352
#define BN_EPS 1e-3f

__device__ float g_emb [NMAX * 32];
__device__ float g_u   [NMAX * 32];
__device__ float g_v   [NMAX * 32];
__device__ float g_max [NMAX * 32];
__device__ float g_sums[128];      // fp32 stats: [0:32) s1, [32:64) q1, [64:96) s2, [96:128) q2

__device__ unsigned g_bar_count = 0;
__device__ unsigned g_bar_gen   = 0;

typedef unsigned long long u64;

__device__ __forceinline__ u64 pack2(float x, float y) {
    u64 r; asm("mov.b64 %0, {%1, %2};" : "=l"(r) : "f"(x), "f"(y)); return r;
}
__device__ __forceinline__ void unpack2(u64 v, float& x, float& y) {
    asm("mov.b64 {%0, %1}, %2;" : "=f"(x), "=f"(y) : "l"(v));
}
__device__ __forceinline__ u64 ffma2(u64 a, u64 b, u64 c) {
    u64 d; asm("fma.rn.f32x2 %0, %1, %2, %3;" : "=l"(d) : "l"(a), "l"(b), "l"(c)); return d;
}
__device__ __forceinline__ u64 add2(u64 a, u64 b) {
    u64 d; asm("add.rn.f32x2 %0, %1, %2;" : "=l"(d) : "l"(a), "l"(b)); return d;
}
__device__ __forceinline__ float eluf(float x) { return x > 0.f ? x : expm1f(x); }

__global__ void k_zero() {
    if (threadIdx.x < 128) g_sums[threadIdx.x] = 0.f;
}

// all blocks must be resident (grid == guaranteed-resident capacity via launch_bounds)
__device__ __forceinline__ void grid_barrier() {
    __syncthreads();
    if (threadIdx.x == 0) {
        __threadfence();
        unsigned gen = *(volatile unsigned*)&g_bar_gen;
        unsigned arrived = atomicAdd(&g_bar_count, 1u);
        if (arrived == gridDim.x - 1) {
            g_bar_count = 0;
            __threadfence();
            atomicAdd(&g_bar_gen, 1u);
        } else {
            while (*(volatile unsigned*)&g_bar_gen == gen) {}
        }
        __threadfence();
    }
    __syncthreads();
}

__device__ __forceinline__ void flush_stats(float accs, float accq, int sumoff) {
    __shared__ float ss[4][32], sq[4][32];
    int lane = threadIdx.x & 31;
    int w    = threadIdx.x >> 5;
    ss[w][lane] = accs;
    sq[w][lane] = accq;
    __syncthreads();
    if (threadIdx.x < 32) {
        float s = 0.f, q = 0.f;
        #pragma unroll
        for (int k = 0; k < 4; k++) { s += ss[k][lane]; q += sq[k][lane]; }
        atomicAdd(&g_sums[sumoff + lane],      s);
        atomicAdd(&g_sums[sumoff + 32 + lane], q);
        __threadfence();
    }
    __syncthreads();
}

// ================= FUSED 1: encode -> BN1 stats -> barrier -> prep ==========
// Hot weights (W_enc, folded W_msg) in REGISTERS; cold small weights in SMEM.
// regs ~90 -> 5 blocks/SM (740-block exactly-resident grid)
__global__ void __launch_bounds__(128, 5) k_enc_prep(
        const float* __restrict__ x_cont, const int* __restrict__ x_cat,
        const float* __restrict__ datanorm,
        const float* __restrict__ W_cont, const float* __restrict__ b_cont,
        const float* __restrict__ emb_charge, const float* __restrict__ emb_pdg,
        const float* __restrict__ W_cat, const float* __restrict__ b_cat,
        const float* __restrict__ W_enc, const float* __restrict__ b_enc,
        const float* __restrict__ g_all, const float* __restrict__ be_all,
        const float* __restrict__ W_msg, int N)
{
    int tid  = threadIdx.x;
    int lane = tid & 31;
    int w    = tid >> 5;
    int l16  = lane & 15;
    bool hi  = lane >= 16;
    int gw   = (blockIdx.x * blockDim.x + tid) >> 5;
    int nw   = (gridDim.x * blockDim.x) >> 5;

    __shared__ __align__(16) u64 sWcat [16][16];   // cold: categorical matvec weights (dup u64)
    __shared__ __align__(16) u64 sWcont[6][16];    // cold: continuous matvec weights (dup u64)
    __shared__ __align__(16) u64 s_c [4][16];
    __shared__ __align__(16) u64 s_x [4][8];
    __shared__ __align__(16) u64 s_in[4][32];
    __shared__ __align__(16) u64 s_h [4][2][32];

    for (int idx = tid; idx < 256; idx += 128) {
        float v = W_cat[idx];
        sWcat[idx >> 4][idx & 15] = pack2(v, v);
    }
    if (tid < 96) {
        float v = W_cont[tid];
        sWcont[tid >> 4][tid & 15] = pack2(v, v);
    }
    __syncthreads();

    // ---------------- phase A: encoder (W_enc in registers) ----------------
    {
        u64 wenc2[32];
        #pragma unroll
        for (int j = 0; j < 32; j++) { float v = W_enc[j * 32 + lane]; wenc2[j] = pack2(v, v); }
        float bcat  = b_cat[l16];
        float bcont = b_cont[l16];
        float benc  = b_enc[lane];
        float dn    = (lane < 6) ? datanorm[lane] : 0.f;

        const float ninf = __int_as_float(0xff800000);
        float accs = 0.f, accq = 0.f;

        for (long long n0 = (long long)gw * 2; n0 < N; n0 += (long long)nw * 2) {
            int na = (int)n0;
            bool hasb = (na + 1 < N);
            int nb = hasb ? na + 1 : na;

            if (!hi) {
                int2 ca = __ldg((const int2*)x_cat + na);
                int2 cb = __ldg((const int2*)x_cat + nb);
                int pa = ca.x < 0 ? -ca.x : ca.x;
                int pb = cb.x < 0 ? -cb.x : cb.x;
                int pia = (pa == 1) ? 0 : (pa == 2) ? 1 : (pa == 11) ? 2 : (pa == 13) ? 3
                        : (pa == 22) ? 4 : (pa == 130) ? 5 : 6;
                int pib = (pb == 1) ? 0 : (pb == 2) ? 1 : (pb == 11) ? 2 : (pb == 13) ? 3
                        : (pb == 22) ? 4 : (pb == 130) ? 5 : 6;
                float c0a = (lane < 8) ? emb_charge[(ca.y + 1) * 8 + lane] : emb_pdg[pia * 8 + lane - 8];
                float c0b = (lane < 8) ? emb_charge[(cb.y + 1) * 8 + lane] : emb_pdg[pib * 8 + lane - 8];
                s_c[w][lane] = pack2(c0a, c0b);
                if (lane < 6) {
                    float xa = x_cont[(long long)na * 6 + lane] * dn;
                    float xb = x_cont[(long long)nb * 6 + lane] * dn;
                    s_x[w][lane] = pack2(xa, xb);
                }
            }
            __syncwarp();

            u64 in2;
            if (!hi) {
                u64 a0 = pack2(bcat, bcat), a1 = pack2(0.f, 0.f);
                const ulonglong2* p = (const ulonglong2*)s_c[w];
                #pragma unroll
                for (int i = 0; i < 4; i++) {
                    ulonglong2 qa = p[i];
                    ulonglong2 qb = p[i + 4];
                    a0 = ffma2(qa.x, sWcat[2 * i][l16], a0);
                    a0 = ffma2(qa.y, sWcat[2 * i + 1][l16], a0);
                    a1 = ffma2(qb.x, sWcat[2 * i + 8][l16], a1);
                    a1 = ffma2(qb.y, sWcat[2 * i + 9][l16], a1);
                }
                u64 acc = add2(a0, a1);
                float v0, v1; unpack2(acc, v0, v1);
                in2 = pack2(eluf(v0), eluf(v1));
            } else {
                u64 acc = pack2(bcont, bcont);
                const ulonglong2* p = (const ulonglong2*)s_x[w];
                #pragma unroll
                for (int i = 0; i < 3; i++) {
                    ulonglong2 q = p[i];
                    acc = ffma2(q.x, sWcont[2 * i][l16], acc);
                    acc = ffma2(q.y, sWcont[2 * i + 1][l16], acc);
                }
                float v0, v1; unpack2(acc, v0, v1);
                in2 = pack2(eluf(v0), eluf(v1));
            }
            s_in[w][lane] = in2;
            __syncwarp();

            u64 a0 = pack2(benc, benc), a1 = pack2(0.f, 0.f);
            {
                const ulonglong2* p = (const ulonglong2*)s_in[w];
                #pragma unroll
                for (int i = 0; i < 8; i++) {
                    ulonglong2 qa = p[i];
                    ulonglong2 qb = p[i + 8];
                    a0 = ffma2(qa.x, wenc2[2 * i], a0);
                    a0 = ffma2(qa.y, wenc2[2 * i + 1], a0);
                    a1 = ffma2(qb.x, wenc2[2 * i + 16], a1);
                    a1 = ffma2(qb.y, wenc2[2 * i + 17], a1);
                }
            }
            u64 acc = add2(a0, a1);
            float ha, hb; unpack2(acc, ha, hb);
            ha = eluf(ha); hb = eluf(hb);

            g_emb[(long long)na * 32 + lane] = ha;
            g_max[(long long)na * 32 + lane] = ninf;
            accs += ha; accq += ha * ha;
            if (hasb) {
                g_emb[(long long)nb * 32 + lane] = hb;
                g_max[(long long)nb * 32 + lane] = ninf;
                accs += hb; accq += hb * hb;
            }
            __syncwarp();
        }
        flush_stats(accs, accq, 0);
    }

    grid_barrier();

    // ---------------- phase B: u,v with BN1 folded (weights in registers) ---
    {
        float wd[32], wb[32];
        #pragma unroll
        for (int j = 0; j < 32; j++) {
            float a = W_msg[j * 32 + lane];
            float b = W_msg[1024 + j * 32 + lane];
            wd[j] = a - b;
            wb[j] = b;
        }
        float m    = g_sums[lane] / (float)N;
        float var  = g_sums[32 + lane] / (float)N - m * m;
        float inv  = rsqrtf(var + BN_EPS);
        float ga   = g_all[lane];
        float scale = ga * inv;
        float shift = be_all[lane] - m * ga * inv;

        float cu = 0.f, cv = 0.f;
        u64 w2[32];
        #pragma unroll
        for (int j = 0; j < 32; j++) {
            float sj = __shfl_sync(0xffffffffu, scale, j);
            float tj = __shfl_sync(0xffffffffu, shift, j);
            cu += tj * wd[j];
            cv += tj * wb[j];
            w2[j] = pack2(wd[j] * sj, wb[j] * sj);
        }
        u64 base = pack2(cu, cv);
        const u64 zz = pack2(0.f, 0.f);

        long long n0 = (long long)gw * 2;
        float ha = (n0 < N) ? g_emb[n0 * 32 + lane] : 0.f;
        float hb = (n0 + 1 < N) ? g_emb[(n0 + 1) * 32 + lane] : ha;

        for (; n0 < N; n0 += (long long)nw * 2) {
            int na = (int)n0;
            bool hasb = (na + 1 < N);
            int nb = hasb ? na + 1 : na;

            s_h[w][0][lane] = pack2(ha, ha);
            s_h[w][1][lane] = pack2(hb, hb);
            __syncwarp();

            long long nn = n0 + (long long)nw * 2;
            float nha = 0.f, nhb = 0.f;
            if (nn < N) {
                nha = g_emb[nn * 32 + lane];
                nhb = (nn + 1 < N) ? g_emb[(nn + 1) * 32 + lane] : nha;
            }

            u64 a0 = base, a1 = zz, b0 = base, b1 = zz;
            const ulonglong2* p0 = (const ulonglong2*)s_h[w][0];
            const ulonglong2* p1 = (const ulonglong2*)s_h[w][1];
            #pragma unroll
            for (int i = 0; i < 8; i++) {
                ulonglong2 qa = p0[i];
                ulonglong2 qb = p0[i + 8];
                a0 = ffma2(qa.x, w2[2 * i], a0);
                a0 = ffma2(qa.y, w2[2 * i + 1], a0);
                a1 = ffma2(qb.x, w2[2 * i + 16], a1);
                a1 = ffma2(qb.y, w2[2 * i + 17], a1);
                ulonglong2 ra = p1[i];
                ulonglong2 rb = p1[i + 8];
                b0 = ffma2(ra.x, w2[2 * i], b0);
                b0 = ffma2(ra.y, w2[2 * i + 1], b0);
                b1 = ffma2(rb.x, w2[2 * i + 16], b1);
                b1 = ffma2(rb.y, w2[2 * i + 17], b1);
            }
            u64 acc0 = add2(a0, a1);
            u64 acc1 = add2(b0, b1);
            float u0, v0; unpack2(acc0, u0, v0);
            g_u[(long long)na * 32 + lane] = u0;
            g_v[(long long)na * 32 + lane] = v0;
            if (hasb) {
                float u1, v1; unpack2(acc1, u1, v1);
                g_u[(long long)nb * 32 + lane] = u1;
                g_v[(long long)nb * 32 + lane] = v1;
            }
            ha = nha; hb = nhb;
            __syncwarp();
        }
    }
}

// ---------------- K3: edge atomic max (proven R11 config) -------------------
__device__ __forceinline__ void amax1(float* a, float v, float c) {
    if (v > c) {
        if (__float_as_int(v) >= 0) atomicMax((int*)a, __float_as_int(v));
        else                        atomicMin((unsigned int*)a, __float_as_uint(v));
    }
}

__global__ void __launch_bounds__(256) k_edge(const int* __restrict__ ei, int E, int NP)
{
    int tid = blockIdx.x * blockDim.x + threadIdx.x;
    int c  = tid & 7;
    int pe = tid >> 3;
    if (pe >= NP) return;
    int e0 = pe * 2;
    bool has1 = (e0 + 1 < E);

    int s0, s1, d0, d1;
    if ((E & 1) == 0) {
        int2 ss = __ldg((const int2*)(ei + e0));
        int2 dd = __ldg((const int2*)(ei + E + e0));
        s0 = ss.x; s1 = ss.y;
        d0 = dd.x; d1 = dd.y;
    } else {
        s0 = __ldg(&ei[e0]);
        d0 = __ldg(&ei[E + e0]);
        s1 = has1 ? __ldg(&ei[e0 + 1])     : s0;
        d1 = has1 ? __ldg(&ei[E + e0 + 1]) : d0;
    }

    const float4* v4 = (const float4*)g_v;
    const float4* m4 = (const float4*)g_max;

    float4 val0 = __ldg(&v4[(long long)s0 * 8 + c]);
    float4 val1 = __ldg(&v4[(long long)s1 * 8 + c]);
    // monotone buffer: stale pre-read only causes a redundant atomic, never a miss
    float4 cur0 = __ldg(&m4[(long long)d0 * 8 + c]);
    float4 cur1 = __ldg(&m4[(long long)d1 * 8 + c]);

    float* a0 = &g_max[(long long)d0 * 32 + c * 4];
    amax1(a0 + 0, val0.x, cur0.x);
    amax1(a0 + 1, val0.y, cur0.y);
    amax1(a0 + 2, val0.z, cur0.z);
    amax1(a0 + 3, val0.w, cur0.w);
    if (has1) {
        float* a1 = &g_max[(long long)d1 * 32 + c * 4];
        amax1(a1 + 0, val1.x, cur1.x);
        amax1(a1 + 1, val1.y, cur1.y);
        amax1(a1 + 2, val1.z, cur1.z);
        amax1(a1 + 3, val1.w, cur1.w);
    }
}

// ========= FUSED 2: agg stats (stash agg) -> barrier -> output MLP ==========
// (R11 measured config: 8 blocks/SM, 1184 blocks, chunk <= 22)
__global__ void __launch_bounds__(128, 8) k_agg_out(
        const float* __restrict__ g_all, const float* __restrict__ be_all,
        const float* __restrict__ b_msg,
        const float* __restrict__ g_conv, const float* __restrict__ be_conv,
        const float* __restrict__ W_o1, const float* __restrict__ b_o1,
        const float* __restrict__ W_o2, const float* __restrict__ b_o2,
        float* __restrict__ out, int N)
{
    int lane = threadIdx.x & 31;
    int w    = threadIdx.x >> 5;
    int l16  = lane & 15;
    int gw   = blockIdx.x * 4 + w;
    int nwarps = gridDim.x * 4;
    int chunk  = (N + nwarps - 1) / nwarps;
    int n_start = gw * chunk;
    int cnt = N - n_start;
    if (cnt > chunk) cnt = chunk;
    if (cnt < 0) cnt = 0;

    __shared__ float s_agg[4][22][32];
    __shared__ float s_h[4][66];

    float bmr = b_msg[lane];

    // ---------------- phase A: agg + BN2 stats, stash agg in smem -----------
    {
        float accs = 0.f, accq = 0.f;
        for (int i = 0; i < cnt; i++) {
            long long n = (long long)(n_start + i);
            float mval = g_max[n * 32 + lane];
            float uval = g_u[n * 32 + lane];
            int m0 = __shfl_sync(0xffffffffu, __float_as_int(mval), 0);
            float x = (m0 == (int)0xff800000) ? 0.f : (uval + bmr + mval);
            s_agg[w][i][lane] = x;
            accs += x;
            accq += x * x;
        }
        flush_stats(accs, accq, 64);
    }

    grid_barrier();

    // ---------------- phase B: residual + output MLP (split-lane) -----------
    {
        float w1[32];
        #pragma unroll
        for (int j = 0; j < 32; j++) w1[j] = W_o1[j * 16 + l16];
        float w2s = W_o2[l16];
        float b1  = b_o1[l16];
        float b2  = b_o2[0];

        float m1    = g_sums[lane] / (float)N;
        float var1  = g_sums[32 + lane] / (float)N - m1 * m1;
        float inv1  = rsqrtf(var1 + BN_EPS);
        float ga    = g_all[lane];
        float scale1 = ga * inv1;
        float shift1 = be_all[lane] - m1 * ga * inv1;

        float m2    = g_sums[64 + lane] / (float)N;
        float var2  = g_sums[96 + lane] / (float)N - m2 * m2;
        float inv2  = rsqrtf(var2 + BN_EPS);
        float gc    = g_conv[lane];
        float scale2 = gc * inv2;
        float shift2 = be_conv[lane] - m2 * gc * inv2;

        int base = (lane < 16) ? 0 : 33;

        for (int i = 0; i < cnt; i += 2) {
            long long na = (long long)(n_start + i);
            bool hasb = (i + 1 < cnt);

            float hraw_a = g_emb[na * 32 + lane];
            float hraw_b = hasb ? g_emb[(na + 1) * 32 + lane] : 0.f;
            float h_a = (hraw_a * scale1 + shift1) + (s_agg[w][i][lane] * scale2 + shift2);
            float h_b = hasb ? (hraw_b * scale1 + shift1) + (s_agg[w][i + 1][lane] * scale2 + shift2) : 0.f;

            s_h[w][lane]      = h_a;
            s_h[w][33 + lane] = h_b;
            __syncwarp();

            float a0 = b1, a1 = 0.f;
            #pragma unroll
            for (int j = 0; j < 16; j++) {
                a0 += s_h[w][base + j]      * w1[j];
                a1 += s_h[w][base + 16 + j] * w1[16 + j];
            }
            float o = eluf(a0 + a1) * w2s;
            #pragma unroll
            for (int off = 1; off < 16; off <<= 1)
                o += __shfl_xor_sync(0xffffffffu, o, off);
            if (lane == 0)          out[na]     = o + b2;
            if (lane == 16 && hasb) out[na + 1] = o + b2;
            __syncwarp();
        }
    }
}

extern "C" void kernel_launch(void* const* d_in, const int* in_sizes, int n_in,
                              void* d_out, int out_size)
{
    const float* x_cont     = (const float*)d_in[0];
    const int*   x_cat      = (const int*)  d_in[1];
    const int*   edge_index = (const int*)  d_in[2];
    const float* datanorm   = (const float*)d_in[4];
    const float* W_cont     = (const float*)d_in[5];
    const float* b_cont     = (const float*)d_in[6];
    const float* emb_charge = (const float*)d_in[7];
    const float* emb_pdg    = (const float*)d_in[8];
    const float* W_cat      = (const float*)d_in[9];
    const float* b_cat      = (const float*)d_in[10];
    const float* W_enc      = (const float*)d_in[11];
    const float* b_enc      = (const float*)d_in[12];
    const float* g_all      = (const float*)d_in[13];
    const float* be_all     = (const float*)d_in[14];
    const float* W_msg      = (const float*)d_in[15];
    const float* b_msg      = (const float*)d_in[16];
    const float* g_conv     = (const float*)d_in[17];
    const float* be_conv    = (const float*)d_in[18];
    const float* W_o1       = (const float*)d_in[19];
    const float* b_o1       = (const float*)d_in[20];
    const float* W_o2       = (const float*)d_in[21];
    const float* b_o2       = (const float*)d_in[22];
    float* out = (float*)d_out;

    int N = in_sizes[0] / 6;
    int E = in_sizes[2] / 2;

    k_zero<<<1, 128>>>();
    k_enc_prep<<<740, 128>>>(x_cont, x_cat, datanorm, W_cont, b_cont,
                             emb_charge, emb_pdg, W_cat, b_cat, W_enc, b_enc,
                             g_all, be_all, W_msg, N);
    int NP = (E + 1) / 2;
    long long tot = (long long)NP * 8;
    int eb = (int)((tot + 255) / 256);
    k_edge<<<eb, 256>>>(edge_index, E, NP);
    k_agg_out<<<1184, 128>>>(g_all, be_all, b_msg, g_conv, be_conv,
                             W_o1, b_o1, W_o2, b_o2, out, N);
}

// round 15
// speedup vs baseline: 1.1589x; 1.0276x over previous
#include <cuda_runtime.h>
#include <math.h>

#define NMAX 100352
#define BN_EPS 1e-3f

__device__ float g_emb [NMAX * 32];
__device__ float g_u   [NMAX * 32];
__device__ unsigned g_v  [NMAX * 32];   // monotone-uint keys of v
__device__ unsigned g_max[NMAX * 32];   // running max in key domain; 0 == empty
__device__ float g_sums[128];           // fp32 stats; ZERO at entry (restored by k_agg_out tail)

__device__ unsigned g_bar_count = 0;
__device__ unsigned g_bar_gen   = 0;
__device__ unsigned g_done      = 0;

typedef unsigned long long u64;

__device__ __forceinline__ u64 pack2(float x, float y) {
    u64 r; asm("mov.b64 %0, {%1, %2};" : "=l"(r) : "f"(x), "f"(y)); return r;
}
__device__ __forceinline__ void unpack2(u64 v, float& x, float& y) {
    asm("mov.b64 {%0, %1}, %2;" : "=f"(x), "=f"(y) : "l"(v));
}
__device__ __forceinline__ u64 ffma2(u64 a, u64 b, u64 c) {
    u64 d; asm("fma.rn.f32x2 %0, %1, %2, %3;" : "=l"(d) : "l"(a), "l"(b), "l"(c)); return d;
}
__device__ __forceinline__ u64 add2(u64 a, u64 b) {
    u64 d; asm("add.rn.f32x2 %0, %1, %2;" : "=l"(d) : "l"(a), "l"(b)); return d;
}
__device__ __forceinline__ float eluf(float x) { return x > 0.f ? x : expm1f(x); }

// order-preserving float -> uint key (max in uint domain == max in float domain)
__device__ __forceinline__ unsigned fkey(float f) {
    int i = __float_as_int(f);
    return (i >= 0) ? ((unsigned)i | 0x80000000u) : ~(unsigned)i;
}
__device__ __forceinline__ float finv(unsigned k) {
    int i = (k & 0x80000000u) ? (int)(k & 0x7FFFFFFFu) : ~(int)k;
    return __int_as_float(i);
}

// all blocks must be resident (grid == guaranteed-resident capacity via launch_bounds)
__device__ __forceinline__ void grid_barrier() {
    __syncthreads();
    if (threadIdx.x == 0) {
        __threadfence();
        unsigned gen = *(volatile unsigned*)&g_bar_gen;
        unsigned arrived = atomicAdd(&g_bar_count, 1u);
        if (arrived == gridDim.x - 1) {
            g_bar_count = 0;
            __threadfence();
            atomicAdd(&g_bar_gen, 1u);
        } else {
            while (*(volatile unsigned*)&g_bar_gen == gen) {}
        }
        __threadfence();
    }
    __syncthreads();
}

__device__ __forceinline__ void flush_stats(float accs, float accq, int sumoff) {
    __shared__ float ss[4][32], sq[4][32];
    int lane = threadIdx.x & 31;
    int w    = threadIdx.x >> 5;
    ss[w][lane] = accs;
    sq[w][lane] = accq;
    __syncthreads();
    if (threadIdx.x < 32) {
        float s = 0.f, q = 0.f;
        #pragma unroll
        for (int k = 0; k < 4; k++) { s += ss[k][lane]; q += sq[k][lane]; }
        atomicAdd(&g_sums[sumoff + lane],      s);
        atomicAdd(&g_sums[sumoff + 32 + lane], q);
        __threadfence();
    }
    __syncthreads();
}

// ================= FUSED 1: encode -> BN1 stats -> barrier -> prep ==========
__global__ void __launch_bounds__(128, 5) k_enc_prep(
        const float* __restrict__ x_cont, const int* __restrict__ x_cat,
        const float* __restrict__ datanorm,
        const float* __restrict__ W_cont, const float* __restrict__ b_cont,
        const float* __restrict__ emb_charge, const float* __restrict__ emb_pdg,
        const float* __restrict__ W_cat, const float* __restrict__ b_cat,
        const float* __restrict__ W_enc, const float* __restrict__ b_enc,
        const float* __restrict__ g_all, const float* __restrict__ be_all,
        const float* __restrict__ W_msg, int N)
{
    int tid  = threadIdx.x;
    int lane = tid & 31;
    int w    = tid >> 5;
    int l16  = lane & 15;
    bool hi  = lane >= 16;
    int gw   = (blockIdx.x * blockDim.x + tid) >> 5;
    int nw   = (gridDim.x * blockDim.x) >> 5;

    __shared__ __align__(16) u64 sWcat [16][16];
    __shared__ __align__(16) u64 sWcont[6][16];
    __shared__ __align__(16) u64 s_c [4][16];
    __shared__ __align__(16) u64 s_x [4][8];
    __shared__ __align__(16) u64 s_in[4][32];
    __shared__ __align__(16) u64 s_h [4][2][32];

    for (int idx = tid; idx < 256; idx += 128) {
        float v = W_cat[idx];
        sWcat[idx >> 4][idx & 15] = pack2(v, v);
    }
    if (tid < 96) {
        float v = W_cont[tid];
        sWcont[tid >> 4][tid & 15] = pack2(v, v);
    }
    __syncthreads();

    // ---------------- phase A: encoder (W_enc in registers) ----------------
    {
        u64 wenc2[32];
        #pragma unroll
        for (int j = 0; j < 32; j++) { float v = W_enc[j * 32 + lane]; wenc2[j] = pack2(v, v); }
        float bcat  = b_cat[l16];
        float bcont = b_cont[l16];
        float benc  = b_enc[lane];
        float dn    = (lane < 6) ? datanorm[lane] : 0.f;

        float accs = 0.f, accq = 0.f;

        for (long long n0 = (long long)gw * 2; n0 < N; n0 += (long long)nw * 2) {
            int na = (int)n0;
            bool hasb = (na + 1 < N);
            int nb = hasb ? na + 1 : na;

            if (!hi) {
                int2 ca = __ldg((const int2*)x_cat + na);
                int2 cb = __ldg((const int2*)x_cat + nb);
                int pa = ca.x < 0 ? -ca.x : ca.x;
                int pb = cb.x < 0 ? -cb.x : cb.x;
                int pia = (pa == 1) ? 0 : (pa == 2) ? 1 : (pa == 11) ? 2 : (pa == 13) ? 3
                        : (pa == 22) ? 4 : (pa == 130) ? 5 : 6;
                int pib = (pb == 1) ? 0 : (pb == 2) ? 1 : (pb == 11) ? 2 : (pb == 13) ? 3
                        : (pb == 22) ? 4 : (pb == 130) ? 5 : 6;
                float c0a = (lane < 8) ? emb_charge[(ca.y + 1) * 8 + lane] : emb_pdg[pia * 8 + lane - 8];
                float c0b = (lane < 8) ? emb_charge[(cb.y + 1) * 8 + lane] : emb_pdg[pib * 8 + lane - 8];
                s_c[w][lane] = pack2(c0a, c0b);
                if (lane < 6) {
                    float xa = x_cont[(long long)na * 6 + lane] * dn;
                    float xb = x_cont[(long long)nb * 6 + lane] * dn;
                    s_x[w][lane] = pack2(xa, xb);
                }
            }
            __syncwarp();

            u64 in2;
            if (!hi) {
                u64 a0 = pack2(bcat, bcat), a1 = pack2(0.f, 0.f);
                const ulonglong2* p = (const ulonglong2*)s_c[w];
                #pragma unroll
                for (int i = 0; i < 4; i++) {
                    ulonglong2 qa = p[i];
                    ulonglong2 qb = p[i + 4];
                    a0 = ffma2(qa.x, sWcat[2 * i][l16], a0);
                    a0 = ffma2(qa.y, sWcat[2 * i + 1][l16], a0);
                    a1 = ffma2(qb.x, sWcat[2 * i + 8][l16], a1);
                    a1 = ffma2(qb.y, sWcat[2 * i + 9][l16], a1);
                }
                u64 acc = add2(a0, a1);
                float v0, v1; unpack2(acc, v0, v1);
                in2 = pack2(eluf(v0), eluf(v1));
            } else {
                u64 acc = pack2(bcont, bcont);
                const ulonglong2* p = (const ulonglong2*)s_x[w];
                #pragma unroll
                for (int i = 0; i < 3; i++) {
                    ulonglong2 q = p[i];
                    acc = ffma2(q.x, sWcont[2 * i][l16], acc);
                    acc = ffma2(q.y, sWcont[2 * i + 1][l16], acc);
                }
                float v0, v1; unpack2(acc, v0, v1);
                in2 = pack2(eluf(v0), eluf(v1));
            }
            s_in[w][lane] = in2;
            __syncwarp();

            u64 a0 = pack2(benc, benc), a1 = pack2(0.f, 0.f);
            {
                const ulonglong2* p = (const ulonglong2*)s_in[w];
                #pragma unroll
                for (int i = 0; i < 8; i++) {
                    ulonglong2 qa = p[i];
                    ulonglong2 qb = p[i + 8];
                    a0 = ffma2(qa.x, wenc2[2 * i], a0);
                    a0 = ffma2(qa.y, wenc2[2 * i + 1], a0);
                    a1 = ffma2(qb.x, wenc2[2 * i + 16], a1);
                    a1 = ffma2(qb.y, wenc2[2 * i + 17], a1);
                }
            }
            u64 acc = add2(a0, a1);
            float ha, hb; unpack2(acc, ha, hb);
            ha = eluf(ha); hb = eluf(hb);

            g_emb[(long long)na * 32 + lane] = ha;
            g_max[(long long)na * 32 + lane] = 0u;   // key-domain "empty"
            accs += ha; accq += ha * ha;
            if (hasb) {
                g_emb[(long long)nb * 32 + lane] = hb;
                g_max[(long long)nb * 32 + lane] = 0u;
                accs += hb; accq += hb * hb;
            }
            __syncwarp();
        }
        flush_stats(accs, accq, 0);
    }

    grid_barrier();

    // ---------------- phase B: u,v with BN1 folded (weights in registers) ---
    {
        float wd[32], wb[32];
        #pragma unroll
        for (int j = 0; j < 32; j++) {
            float a = W_msg[j * 32 + lane];
            float b = W_msg[1024 + j * 32 + lane];
            wd[j] = a - b;
            wb[j] = b;
        }
        float m    = g_sums[lane] / (float)N;
        float var  = g_sums[32 + lane] / (float)N - m * m;
        float inv  = rsqrtf(var + BN_EPS);
        float ga   = g_all[lane];
        float scale = ga * inv;
        float shift = be_all[lane] - m * ga * inv;

        float cu = 0.f, cv = 0.f;
        u64 w2[32];
        #pragma unroll
        for (int j = 0; j < 32; j++) {
            float sj = __shfl_sync(0xffffffffu, scale, j);
            float tj = __shfl_sync(0xffffffffu, shift, j);
            cu += tj * wd[j];
            cv += tj * wb[j];
            w2[j] = pack2(wd[j] * sj, wb[j] * sj);
        }
        u64 base = pack2(cu, cv);
        const u64 zz = pack2(0.f, 0.f);

        long long n0 = (long long)gw * 2;
        float ha = (n0 < N) ? g_emb[n0 * 32 + lane] : 0.f;
        float hb = (n0 + 1 < N) ? g_emb[(n0 + 1) * 32 + lane] : ha;

        for (; n0 < N; n0 += (long long)nw * 2) {
            int na = (int)n0;
            bool hasb = (na + 1 < N);
            int nb = hasb ? na + 1 : na;

            s_h[w][0][lane] = pack2(ha, ha);
            s_h[w][1][lane] = pack2(hb, hb);
            __syncwarp();

            long long nn = n0 + (long long)nw * 2;
            float nha = 0.f, nhb = 0.f;
            if (nn < N) {
                nha = g_emb[nn * 32 + lane];
                nhb = (nn + 1 < N) ? g_emb[(nn + 1) * 32 + lane] : nha;
            }

            u64 a0 = base, a1 = zz, b0 = base, b1 = zz;
            const ulonglong2* p0 = (const ulonglong2*)s_h[w][0];
            const ulonglong2* p1 = (const ulonglong2*)s_h[w][1];
            #pragma unroll
            for (int i = 0; i < 8; i++) {
                ulonglong2 qa = p0[i];
                ulonglong2 qb = p0[i + 8];
                a0 = ffma2(qa.x, w2[2 * i], a0);
                a0 = ffma2(qa.y, w2[2 * i + 1], a0);
                a1 = ffma2(qb.x, w2[2 * i + 16], a1);
                a1 = ffma2(qb.y, w2[2 * i + 17], a1);
                ulonglong2 ra = p1[i];
                ulonglong2 rb = p1[i + 8];
                b0 = ffma2(ra.x, w2[2 * i], b0);
                b0 = ffma2(ra.y, w2[2 * i + 1], b0);
                b1 = ffma2(rb.x, w2[2 * i + 16], b1);
                b1 = ffma2(rb.y, w2[2 * i + 17], b1);
            }
            u64 acc0 = add2(a0, a1);
            u64 acc1 = add2(b0, b1);
            float u0, v0; unpack2(acc0, u0, v0);
            g_u[(long long)na * 32 + lane] = u0;
            g_v[(long long)na * 32 + lane] = fkey(v0);   // store key domain
            if (hasb) {
                float u1, v1; unpack2(acc1, u1, v1);
                g_u[(long long)nb * 32 + lane] = u1;
                g_v[(long long)nb * 32 + lane] = fkey(v1);
            }
            ha = nha; hb = nhb;
            __syncwarp();
        }
    }
}

// ---------------- K3: edge atomic max (uint key domain) ---------------------
__global__ void __launch_bounds__(256) k_edge(const int* __restrict__ ei, int E, int NP)
{
    int tid = blockIdx.x * blockDim.x + threadIdx.x;
    int c  = tid & 7;
    int pe = tid >> 3;
    if (pe >= NP) return;
    int e0 = pe * 2;
    bool has1 = (e0 + 1 < E);

    int s0, s1, d0, d1;
    if ((E & 1) == 0) {
        int2 ss = __ldg((const int2*)(ei + e0));
        int2 dd = __ldg((const int2*)(ei + E + e0));
        s0 = ss.x; s1 = ss.y;
        d0 = dd.x; d1 = dd.y;
    } else {
        s0 = __ldg(&ei[e0]);
        d0 = __ldg(&ei[E + e0]);
        s1 = has1 ? __ldg(&ei[e0 + 1])     : s0;
        d1 = has1 ? __ldg(&ei[E + e0 + 1]) : d0;
    }

    const uint4* v4 = (const uint4*)g_v;
    const uint4* m4 = (const uint4*)g_max;

    uint4 val0 = __ldg(&v4[(long long)s0 * 8 + c]);
    uint4 val1 = __ldg(&v4[(long long)s1 * 8 + c]);
    // monotone buffer: stale pre-read only causes a redundant atomic, never a miss
    uint4 cur0 = __ldg(&m4[(long long)d0 * 8 + c]);
    uint4 cur1 = __ldg(&m4[(long long)d1 * 8 + c]);

    unsigned* a0 = &g_max[(long long)d0 * 32 + c * 4];
    if (val0.x > cur0.x) atomicMax(a0 + 0, val0.x);
    if (val0.y > cur0.y) atomicMax(a0 + 1, val0.y);
    if (val0.z > cur0.z) atomicMax(a0 + 2, val0.z);
    if (val0.w > cur0.w) atomicMax(a0 + 3, val0.w);
    if (has1) {
        unsigned* a1 = &g_max[(long long)d1 * 32 + c * 4];
        if (val1.x > cur1.x) atomicMax(a1 + 0, val1.x);
        if (val1.y > cur1.y) atomicMax(a1 + 1, val1.y);
        if (val1.z > cur1.z) atomicMax(a1 + 2, val1.z);
        if (val1.w > cur1.w) atomicMax(a1 + 3, val1.w);
    }
}

// ========= FUSED 2: agg stats (stash agg) -> barrier -> output MLP ==========
__global__ void __launch_bounds__(128, 8) k_agg_out(
        const float* __restrict__ g_all, const float* __restrict__ be_all,
        const float* __restrict__ b_msg,
        const float* __restrict__ g_conv, const float* __restrict__ be_conv,
        const float* __restrict__ W_o1, const float* __restrict__ b_o1,
        const float* __restrict__ W_o2, const float* __restrict__ b_o2,
        float* __restrict__ out, int N)
{
    int lane = threadIdx.x & 31;
    int w    = threadIdx.x >> 5;
    int l16  = lane & 15;
    int gw   = blockIdx.x * 4 + w;
    int nwarps = gridDim.x * 4;
    int chunk  = (N + nwarps - 1) / nwarps;
    int n_start = gw * chunk;
    int cnt = N - n_start;
    if (cnt > chunk) cnt = chunk;
    if (cnt < 0) cnt = 0;

    __shared__ float s_agg[4][22][32];
    __shared__ float s_h[4][66];

    float bmr = b_msg[lane];

    // ---------------- phase A: agg + BN2 stats, stash agg in smem -----------
    {
        float accs = 0.f, accq = 0.f;
        for (int i = 0; i < cnt; i++) {
            long long n = (long long)(n_start + i);
            unsigned key = g_max[n * 32 + lane];
            float uval = g_u[n * 32 + lane];
            unsigned k0 = __shfl_sync(0xffffffffu, key, 0);
            float x = (k0 == 0u) ? 0.f : (uval + bmr + finv(key));
            s_agg[w][i][lane] = x;
            accs += x;
            accq += x * x;
        }
        flush_stats(accs, accq, 64);
    }

    grid_barrier();

    // ---------------- phase B: residual + output MLP (split-lane) -----------
    {
        float w1[32];
        #pragma unroll
        for (int j = 0; j < 32; j++) w1[j] = W_o1[j * 16 + l16];
        float w2s = W_o2[l16];
        float b1  = b_o1[l16];
        float b2  = b_o2[0];

        float m1    = g_sums[lane] / (float)N;
        float var1  = g_sums[32 + lane] / (float)N - m1 * m1;
        float inv1  = rsqrtf(var1 + BN_EPS);
        float ga    = g_all[lane];
        float scale1 = ga * inv1;
        float shift1 = be_all[lane] - m1 * ga * inv1;

        float m2    = g_sums[64 + lane] / (float)N;
        float var2  = g_sums[96 + lane] / (float)N - m2 * m2;
        float inv2  = rsqrtf(var2 + BN_EPS);
        float gc    = g_conv[lane];
        float scale2 = gc * inv2;
        float shift2 = be_conv[lane] - m2 * gc * inv2;

        int base = (lane < 16) ? 0 : 33;

        for (int i = 0; i < cnt; i += 2) {
            long long na = (long long)(n_start + i);
            bool hasb = (i + 1 < cnt);

            float hraw_a = g_emb[na * 32 + lane];
            float hraw_b = hasb ? g_emb[(na + 1) * 32 + lane] : 0.f;
            float h_a = (hraw_a * scale1 + shift1) + (s_agg[w][i][lane] * scale2 + shift2);
            float h_b = hasb ? (hraw_b * scale1 + shift1) + (s_agg[w][i + 1][lane] * scale2 + shift2) : 0.f;

            s_h[w][lane]      = h_a;
            s_h[w][33 + lane] = h_b;
            __syncwarp();

            float a0 = b1, a1 = 0.f;
            #pragma unroll
            for (int j = 0; j < 16; j++) {
                a0 += s_h[w][base + j]      * w1[j];
                a1 += s_h[w][base + 16 + j] * w1[16 + j];
            }
            float o = eluf(a0 + a1) * w2s;
            #pragma unroll
            for (int off = 1; off < 16; off <<= 1)
                o += __shfl_xor_sync(0xffffffffu, o, off);
            if (lane == 0)          out[na]     = o + b2;
            if (lane == 16 && hasb) out[na + 1] = o + b2;
            __syncwarp();
        }
    }

    // ----- tail: last block to finish restores g_sums == 0 for next replay --
    __syncthreads();
    if (threadIdx.x == 0) {
        __threadfence();
        unsigned t = atomicAdd(&g_done, 1u);
        if (t == gridDim.x - 1) {
            g_done = 0;
            #pragma unroll
            for (int i = 0; i < 128; i++) g_sums[i] = 0.f;
            __threadfence();
        }
    }
}

extern "C" void kernel_launch(void* const* d_in, const int* in_sizes, int n_in,
                              void* d_out, int out_size)
{
    const float* x_cont     = (const float*)d_in[0];
    const int*   x_cat      = (const int*)  d_in[1];
    const int*   edge_index = (const int*)  d_in[2];
    const float* datanorm   = (const float*)d_in[4];
    const float* W_cont     = (const float*)d_in[5];
    const float* b_cont     = (const float*)d_in[6];
    const float* emb_charge = (const float*)d_in[7];
    const float* emb_pdg    = (const float*)d_in[8];
    const float* W_cat      = (const float*)d_in[9];
    const float* b_cat      = (const float*)d_in[10];
    const float* W_enc      = (const float*)d_in[11];
    const float* b_enc      = (const float*)d_in[12];
    const float* g_all      = (const float*)d_in[13];
    const float* be_all     = (const float*)d_in[14];
    const float* W_msg      = (const float*)d_in[15];
    const float* b_msg      = (const float*)d_in[16];
    const float* g_conv     = (const float*)d_in[17];
    const float* be_conv    = (const float*)d_in[18];
    const float* W_o1       = (const float*)d_in[19];
    const float* b_o1       = (const float*)d_in[20];
    const float* W_o2       = (const float*)d_in[21];
    const float* b_o2       = (const float*)d_in[22];
    float* out = (float*)d_out;

    int N = in_sizes[0] / 6;
    int E = in_sizes[2] / 2;

    k_enc_prep<<<740, 128>>>(x_cont, x_cat, datanorm, W_cont, b_cont,
                             emb_charge, emb_pdg, W_cat, b_cat, W_enc, b_enc,
                             g_all, be_all, W_msg, N);
    int NP = (E + 1) / 2;
    long long tot = (long long)NP * 8;
    int eb = (int)((tot + 255) / 256);
    k_edge<<<eb, 256>>>(edge_index, E, NP);
    k_agg_out<<<1184, 128>>>(g_all, be_all, b_msg, g_conv, be_conv,
                             W_o1, b_o1, W_o2, b_o2, out, N);
}

// round 16
// speedup vs baseline: 1.2390x; 1.0692x over previous
#include <cuda_runtime.h>
#include <math.h>

#define NMAX 100352
#define BN_EPS 1e-3f

__device__ float g_emb [NMAX * 32];
__device__ float g_u   [NMAX * 32];
__device__ unsigned g_v  [NMAX * 32];   // monotone-uint keys of v
__device__ unsigned g_max[NMAX * 32];   // running max in key domain; 0 == empty
__device__ float g_sums[128];           // fp32 stats; ZERO at entry (restored by k_agg_out tail)

__device__ unsigned g_bar_count = 0;
__device__ unsigned g_bar_gen   = 0;
__device__ unsigned g_done      = 0;

typedef unsigned long long u64;

__device__ __forceinline__ u64 pack2(float x, float y) {
    u64 r; asm("mov.b64 %0, {%1, %2};" : "=l"(r) : "f"(x), "f"(y)); return r;
}
__device__ __forceinline__ void unpack2(u64 v, float& x, float& y) {
    asm("mov.b64 {%0, %1}, %2;" : "=f"(x), "=f"(y) : "l"(v));
}
__device__ __forceinline__ u64 ffma2(u64 a, u64 b, u64 c) {
    u64 d; asm("fma.rn.f32x2 %0, %1, %2, %3;" : "=l"(d) : "l"(a), "l"(b), "l"(c)); return d;
}
__device__ __forceinline__ u64 add2(u64 a, u64 b) {
    u64 d; asm("add.rn.f32x2 %0, %1, %2;" : "=l"(d) : "l"(a), "l"(b)); return d;
}
__device__ __forceinline__ float eluf(float x) { return x > 0.f ? x : expm1f(x); }

// order-preserving float -> uint key
__device__ __forceinline__ unsigned fkey(float f) {
    int i = __float_as_int(f);
    return (i >= 0) ? ((unsigned)i | 0x80000000u) : ~(unsigned)i;
}
__device__ __forceinline__ float finv(unsigned k) {
    int i = (k & 0x80000000u) ? (int)(k & 0x7FFFFFFFu) : ~(int)k;
    return __int_as_float(i);
}

// all blocks must be resident (grid == guaranteed-resident capacity via launch_bounds)
__device__ __forceinline__ void grid_barrier() {
    __syncthreads();
    if (threadIdx.x == 0) {
        __threadfence();
        unsigned gen = *(volatile unsigned*)&g_bar_gen;
        unsigned arrived = atomicAdd(&g_bar_count, 1u);
        if (arrived == gridDim.x - 1) {
            g_bar_count = 0;
            __threadfence();
            atomicAdd(&g_bar_gen, 1u);
        } else {
            while (*(volatile unsigned*)&g_bar_gen == gen) {}
        }
        __threadfence();
    }
    __syncthreads();
}

__device__ __forceinline__ void flush_stats(float accs, float accq, int sumoff) {
    __shared__ float ss[4][32], sq[4][32];
    int lane = threadIdx.x & 31;
    int w    = threadIdx.x >> 5;
    ss[w][lane] = accs;
    sq[w][lane] = accq;
    __syncthreads();
    if (threadIdx.x < 32) {
        float s = 0.f, q = 0.f;
        #pragma unroll
        for (int k = 0; k < 4; k++) { s += ss[k][lane]; q += sq[k][lane]; }
        atomicAdd(&g_sums[sumoff + lane],      s);
        atomicAdd(&g_sums[sumoff + 32 + lane], q);
        __threadfence();
    }
    __syncthreads();
}

// ================= FUSED 1: encode -> BN1 stats -> barrier -> prep ==========
__global__ void __launch_bounds__(128, 5) k_enc_prep(
        const float* __restrict__ x_cont, const int* __restrict__ x_cat,
        const float* __restrict__ datanorm,
        const float* __restrict__ W_cont, const float* __restrict__ b_cont,
        const float* __restrict__ emb_charge, const float* __restrict__ emb_pdg,
        const float* __restrict__ W_cat, const float* __restrict__ b_cat,
        const float* __restrict__ W_enc, const float* __restrict__ b_enc,
        const float* __restrict__ g_all, const float* __restrict__ be_all,
        const float* __restrict__ W_msg, int N)
{
    int tid  = threadIdx.x;
    int lane = tid & 31;
    int w    = tid >> 5;
    int l16  = lane & 15;
    bool hi  = lane >= 16;
    int gw   = (blockIdx.x * blockDim.x + tid) >> 5;
    int nw   = (gridDim.x * blockDim.x) >> 5;

    // unified first-layer weights: cols 0..15 = W_cat col, cols 16..31 = W_cont col (rows >=6 zero)
    __shared__ __align__(16) u64 sW01[16][32];
    __shared__ __align__(16) u64 s_c  [4][16];   // cat input staging (lanes<16 read)
    __shared__ __align__(16) u64 s_x16[4][16];   // cont input staging, rows 6..15 stay zero
    __shared__ __align__(16) u64 s_in [4][32];
    __shared__ __align__(16) u64 s_h  [4][2][32];

    for (int idx = tid; idx < 512; idx += 128) {
        int j = idx >> 5, col = idx & 31;
        float v;
        if (col < 16)      v = W_cat[j * 16 + col];
        else if (j < 6)    v = W_cont[j * 16 + (col - 16)];
        else               v = 0.f;
        sW01[j][col] = pack2(v, v);
    }
    if (lane < 16) s_x16[w][lane] = 0ull;   // zero-pad; rows 6..15 never rewritten
    __syncthreads();

    // ---------------- phase A: encoder (W_enc in registers) ----------------
    {
        u64 wenc2[32];
        #pragma unroll
        for (int j = 0; j < 32; j++) { float v = W_enc[j * 32 + lane]; wenc2[j] = pack2(v, v); }
        float bin  = hi ? b_cont[l16] : b_cat[l16];
        float benc = b_enc[lane];
        float dn   = (lane < 6) ? datanorm[lane] : 0.f;

        float accs = 0.f, accq = 0.f;

        for (int n0 = gw * 2; n0 < N; n0 += nw * 2) {
            int na = n0;
            bool hasb = (na + 1 < N);
            int nb = hasb ? na + 1 : na;

            if (!hi) {
                int2 ca = __ldg((const int2*)x_cat + na);
                int2 cb = __ldg((const int2*)x_cat + nb);
                int pa = ca.x < 0 ? -ca.x : ca.x;
                int pb = cb.x < 0 ? -cb.x : cb.x;
                int pia = (pa == 1) ? 0 : (pa == 2) ? 1 : (pa == 11) ? 2 : (pa == 13) ? 3
                        : (pa == 22) ? 4 : (pa == 130) ? 5 : 6;
                int pib = (pb == 1) ? 0 : (pb == 2) ? 1 : (pb == 11) ? 2 : (pb == 13) ? 3
                        : (pb == 22) ? 4 : (pb == 130) ? 5 : 6;
                float c0a = (lane < 8) ? emb_charge[(ca.y + 1) * 8 + lane] : emb_pdg[pia * 8 + lane - 8];
                float c0b = (lane < 8) ? emb_charge[(cb.y + 1) * 8 + lane] : emb_pdg[pib * 8 + lane - 8];
                s_c[w][lane] = pack2(c0a, c0b);
                if (lane < 6) {
                    float xa = x_cont[na * 6 + lane] * dn;
                    float xb = x_cont[nb * 6 + lane] * dn;
                    s_x16[w][lane] = pack2(xa, xb);
                }
            }
            __syncwarp();

            // unified first-layer matvec (no divergence)
            u64 in2;
            {
                const ulonglong2* pin = (const ulonglong2*)(hi ? s_x16[w] : s_c[w]);
                u64 a0 = pack2(bin, bin), a1 = pack2(0.f, 0.f);
                #pragma unroll
                for (int i = 0; i < 4; i++) {
                    ulonglong2 qa = pin[i];
                    ulonglong2 qb = pin[i + 4];
                    a0 = ffma2(qa.x, sW01[2 * i][lane], a0);
                    a0 = ffma2(qa.y, sW01[2 * i + 1][lane], a0);
                    a1 = ffma2(qb.x, sW01[2 * i + 8][lane], a1);
                    a1 = ffma2(qb.y, sW01[2 * i + 9][lane], a1);
                }
                u64 acc = add2(a0, a1);
                float v0, v1; unpack2(acc, v0, v1);
                in2 = pack2(eluf(v0), eluf(v1));
            }
            s_in[w][lane] = in2;
            __syncwarp();

            u64 a0 = pack2(benc, benc), a1 = pack2(0.f, 0.f);
            {
                const ulonglong2* p = (const ulonglong2*)s_in[w];
                #pragma unroll
                for (int i = 0; i < 8; i++) {
                    ulonglong2 qa = p[i];
                    ulonglong2 qb = p[i + 8];
                    a0 = ffma2(qa.x, wenc2[2 * i], a0);
                    a0 = ffma2(qa.y, wenc2[2 * i + 1], a0);
                    a1 = ffma2(qb.x, wenc2[2 * i + 16], a1);
                    a1 = ffma2(qb.y, wenc2[2 * i + 17], a1);
                }
            }
            u64 acc = add2(a0, a1);
            float ha, hb; unpack2(acc, ha, hb);
            ha = eluf(ha); hb = eluf(hb);

            int oa = na * 32 + lane;
            int ob = nb * 32 + lane;
            g_emb[oa] = ha;
            g_max[oa] = 0u;
            accs += ha; accq += ha * ha;
            if (hasb) {
                g_emb[ob] = hb;
                g_max[ob] = 0u;
                accs += hb; accq += hb * hb;
            }
            __syncwarp();
        }
        flush_stats(accs, accq, 0);
    }

    grid_barrier();

    // ---------------- phase B: u,v with BN1 folded (weights in registers) ---
    {
        float wd[32], wb[32];
        #pragma unroll
        for (int j = 0; j < 32; j++) {
            float a = W_msg[j * 32 + lane];
            float b = W_msg[1024 + j * 32 + lane];
            wd[j] = a - b;
            wb[j] = b;
        }
        float m    = g_sums[lane] / (float)N;
        float var  = g_sums[32 + lane] / (float)N - m * m;
        float inv  = rsqrtf(var + BN_EPS);
        float ga   = g_all[lane];
        float scale = ga * inv;
        float shift = be_all[lane] - m * ga * inv;

        float cu = 0.f, cv = 0.f;
        u64 w2[32];
        #pragma unroll
        for (int j = 0; j < 32; j++) {
            float sj = __shfl_sync(0xffffffffu, scale, j);
            float tj = __shfl_sync(0xffffffffu, shift, j);
            cu += tj * wd[j];
            cv += tj * wb[j];
            w2[j] = pack2(wd[j] * sj, wb[j] * sj);
        }
        u64 base = pack2(cu, cv);
        const u64 zz = pack2(0.f, 0.f);

        int n0 = gw * 2;
        float ha = (n0 < N) ? g_emb[n0 * 32 + lane] : 0.f;
        float hb = (n0 + 1 < N) ? g_emb[(n0 + 1) * 32 + lane] : ha;

        for (; n0 < N; n0 += nw * 2) {
            int na = n0;
            bool hasb = (na + 1 < N);
            int nb = hasb ? na + 1 : na;

            s_h[w][0][lane] = pack2(ha, ha);
            s_h[w][1][lane] = pack2(hb, hb);
            __syncwarp();

            int nn = n0 + nw * 2;
            float nha = 0.f, nhb = 0.f;
            if (nn < N) {
                nha = g_emb[nn * 32 + lane];
                nhb = (nn + 1 < N) ? g_emb[(nn + 1) * 32 + lane] : nha;
            }

            u64 a0 = base, a1 = zz, b0 = base, b1 = zz;
            const ulonglong2* p0 = (const ulonglong2*)s_h[w][0];
            const ulonglong2* p1 = (const ulonglong2*)s_h[w][1];
            #pragma unroll
            for (int i = 0; i < 8; i++) {
                ulonglong2 qa = p0[i];
                ulonglong2 qb = p0[i + 8];
                a0 = ffma2(qa.x, w2[2 * i], a0);
                a0 = ffma2(qa.y, w2[2 * i + 1], a0);
                a1 = ffma2(qb.x, w2[2 * i + 16], a1);
                a1 = ffma2(qb.y, w2[2 * i + 17], a1);
                ulonglong2 ra = p1[i];
                ulonglong2 rb = p1[i + 8];
                b0 = ffma2(ra.x, w2[2 * i], b0);
                b0 = ffma2(ra.y, w2[2 * i + 1], b0);
                b1 = ffma2(rb.x, w2[2 * i + 16], b1);
                b1 = ffma2(rb.y, w2[2 * i + 17], b1);
            }
            u64 acc0 = add2(a0, a1);
            u64 acc1 = add2(b0, b1);
            float u0, v0; unpack2(acc0, u0, v0);
            int oa = na * 32 + lane;
            g_u[oa] = u0;
            g_v[oa] = fkey(v0);
            if (hasb) {
                float u1, v1; unpack2(acc1, u1, v1);
                int ob = nb * 32 + lane;
                g_u[ob] = u1;
                g_v[ob] = fkey(v1);
            }
            ha = nha; hb = nhb;
            __syncwarp();
        }
    }
}

// ---------------- K3: edge atomic max (uint key domain, int indexing) -------
__global__ void __launch_bounds__(256) k_edge(const int* __restrict__ ei, int E, int NP)
{
    int tid = blockIdx.x * blockDim.x + threadIdx.x;
    int c  = tid & 7;
    int pe = tid >> 3;
    if (pe >= NP) return;
    int e0 = pe * 2;
    bool has1 = (e0 + 1 < E);

    int s0, s1, d0, d1;
    if ((E & 1) == 0) {
        int2 ss = __ldg((const int2*)(ei + e0));
        int2 dd = __ldg((const int2*)(ei + E + e0));
        s0 = ss.x; s1 = ss.y;
        d0 = dd.x; d1 = dd.y;
    } else {
        s0 = __ldg(&ei[e0]);
        d0 = __ldg(&ei[E + e0]);
        s1 = has1 ? __ldg(&ei[e0 + 1])     : s0;
        d1 = has1 ? __ldg(&ei[E + e0 + 1]) : d0;
    }

    const uint4* v4 = (const uint4*)g_v;
    const uint4* m4 = (const uint4*)g_max;

    uint4 val0 = __ldg(&v4[s0 * 8 + c]);
    uint4 val1 = __ldg(&v4[s1 * 8 + c]);
    // monotone buffer: stale pre-read only causes a redundant atomic, never a miss
    uint4 cur0 = __ldg(&m4[d0 * 8 + c]);
    uint4 cur1 = __ldg(&m4[d1 * 8 + c]);

    unsigned* a0 = &g_max[d0 * 32 + c * 4];
    if (val0.x > cur0.x) atomicMax(a0 + 0, val0.x);
    if (val0.y > cur0.y) atomicMax(a0 + 1, val0.y);
    if (val0.z > cur0.z) atomicMax(a0 + 2, val0.z);
    if (val0.w > cur0.w) atomicMax(a0 + 3, val0.w);
    if (has1) {
        unsigned* a1 = &g_max[d1 * 32 + c * 4];
        if (val1.x > cur1.x) atomicMax(a1 + 0, val1.x);
        if (val1.y > cur1.y) atomicMax(a1 + 1, val1.y);
        if (val1.z > cur1.z) atomicMax(a1 + 2, val1.z);
        if (val1.w > cur1.w) atomicMax(a1 + 3, val1.w);
    }
}

// ========= FUSED 2: agg stats (stash agg) -> barrier -> output MLP ==========
__global__ void __launch_bounds__(128, 8) k_agg_out(
        const float* __restrict__ g_all, const float* __restrict__ be_all,
        const float* __restrict__ b_msg,
        const float* __restrict__ g_conv, const float* __restrict__ be_conv,
        const float* __restrict__ W_o1, const float* __restrict__ b_o1,
        const float* __restrict__ W_o2, const float* __restrict__ b_o2,
        float* __restrict__ out, int N)
{
    int lane = threadIdx.x & 31;
    int w    = threadIdx.x >> 5;
    int l16  = lane & 15;
    int gw   = blockIdx.x * 4 + w;
    int nwarps = gridDim.x * 4;
    int chunk  = (N + nwarps - 1) / nwarps;
    int n_start = gw * chunk;
    int cnt = N - n_start;
    if (cnt > chunk) cnt = chunk;
    if (cnt < 0) cnt = 0;

    __shared__ float s_agg[4][22][32];
    __shared__ float s_h[4][66];

    float bmr = b_msg[lane];

    // ---------------- phase A: agg + BN2 stats, stash agg in smem -----------
    {
        float accs = 0.f, accq = 0.f;
        const unsigned* pm = &g_max[n_start * 32 + lane];
        const float*    pu = &g_u  [n_start * 32 + lane];
        for (int i = 0; i < cnt; i++) {
            unsigned key = pm[i * 32];
            float uval = pu[i * 32];
            unsigned k0 = __shfl_sync(0xffffffffu, key, 0);
            float x = (k0 == 0u) ? 0.f : (uval + bmr + finv(key));
            s_agg[w][i][lane] = x;
            accs += x;
            accq += x * x;
        }
        flush_stats(accs, accq, 64);
    }

    grid_barrier();

    // ---------------- phase B: residual + output MLP (split-lane) -----------
    {
        float w1[32];
        #pragma unroll
        for (int j = 0; j < 32; j++) w1[j] = W_o1[j * 16 + l16];
        float w2s = W_o2[l16];
        float b1  = b_o1[l16];
        float b2  = b_o2[0];

        float m1    = g_sums[lane] / (float)N;
        float var1  = g_sums[32 + lane] / (float)N - m1 * m1;
        float inv1  = rsqrtf(var1 + BN_EPS);
        float ga    = g_all[lane];
        float scale1 = ga * inv1;
        float shift1 = be_all[lane] - m1 * ga * inv1;

        float m2    = g_sums[64 + lane] / (float)N;
        float var2  = g_sums[96 + lane] / (float)N - m2 * m2;
        float inv2  = rsqrtf(var2 + BN_EPS);
        float gc    = g_conv[lane];
        float scale2 = gc * inv2;
        float shift2 = be_conv[lane] - m2 * gc * inv2;

        int base = (lane < 16) ? 0 : 33;

        for (int i = 0; i < cnt; i += 2) {
            int na = n_start + i;
            bool hasb = (i + 1 < cnt);

            float hraw_a = g_emb[na * 32 + lane];
            float hraw_b = hasb ? g_emb[(na + 1) * 32 + lane] : 0.f;
            float h_a = (hraw_a * scale1 + shift1) + (s_agg[w][i][lane] * scale2 + shift2);
            float h_b = hasb ? (hraw_b * scale1 + shift1) + (s_agg[w][i + 1][lane] * scale2 + shift2) : 0.f;

            s_h[w][lane]      = h_a;
            s_h[w][33 + lane] = h_b;
            __syncwarp();

            float a0 = b1, a1 = 0.f;
            #pragma unroll
            for (int j = 0; j < 16; j++) {
                a0 += s_h[w][base + j]      * w1[j];
                a1 += s_h[w][base + 16 + j] * w1[16 + j];
            }
            float o = eluf(a0 + a1) * w2s;
            #pragma unroll
            for (int off = 1; off < 16; off <<= 1)
                o += __shfl_xor_sync(0xffffffffu, o, off);
            if (lane == 0)          out[na]     = o + b2;
            if (lane == 16 && hasb) out[na + 1] = o + b2;
            __syncwarp();
        }
    }

    // ----- tail: last block to finish restores g_sums == 0 for next replay --
    __syncthreads();
    if (threadIdx.x == 0) {
        __threadfence();
        unsigned t = atomicAdd(&g_done, 1u);
        if (t == gridDim.x - 1) {
            g_done = 0;
            #pragma unroll
            for (int i = 0; i < 128; i++) g_sums[i] = 0.f;
            __threadfence();
        }
    }
}

extern "C" void kernel_launch(void* const* d_in, const int* in_sizes, int n_in,
                              void* d_out, int out_size)
{
    const float* x_cont     = (const float*)d_in[0];
    const int*   x_cat      = (const int*)  d_in[1];
    const int*   edge_index = (const int*)  d_in[2];
    const float* datanorm   = (const float*)d_in[4];
    const float* W_cont     = (const float*)d_in[5];
    const float* b_cont     = (const float*)d_in[6];
    const float* emb_charge = (const float*)d_in[7];
    const float* emb_pdg    = (const float*)d_in[8];
    const float* W_cat      = (const float*)d_in[9];
    const float* b_cat      = (const float*)d_in[10];
    const float* W_enc      = (const float*)d_in[11];
    const float* b_enc      = (const float*)d_in[12];
    const float* g_all      = (const float*)d_in[13];
    const float* be_all     = (const float*)d_in[14];
    const float* W_msg      = (const float*)d_in[15];
    const float* b_msg      = (const float*)d_in[16];
    const float* g_conv     = (const float*)d_in[17];
    const float* be_conv    = (const float*)d_in[18];
    const float* W_o1       = (const float*)d_in[19];
    const float* b_o1       = (const float*)d_in[20];
    const float* W_o2       = (const float*)d_in[21];
    const float* b_o2       = (const float*)d_in[22];
    float* out = (float*)d_out;

    int N = in_sizes[0] / 6;
    int E = in_sizes[2] / 2;

    k_enc_prep<<<740, 128>>>(x_cont, x_cat, datanorm, W_cont, b_cont,
                             emb_charge, emb_pdg, W_cat, b_cat, W_enc, b_enc,
                             g_all, be_all, W_msg, N);
    int NP = (E + 1) / 2;
    long long tot = (long long)NP * 8;
    int eb = (int)((tot + 255) / 256);
    k_edge<<<eb, 256>>>(edge_index, E, NP);
    k_agg_out<<<1184, 128>>>(g_all, be_all, b_msg, g_conv, be_conv,
                             W_o1, b_o1, W_o2, b_o2, out, N);
}